// round 16
// baseline (speedup 1.0000x reference)
#include <cuda_runtime.h>
#include <cstdint>

#define L      8192
#define KK     31
#define HALF   15
#define NT     512
#define NW     16                          // warps per CTA
#define CP     16                          // output pairs per thread
#define ULEN   (L + 2*HALF)                // 8222 pairs incl zero halos
#define PHYS64 (ULEN + (ULEN >> 4) + 2)    // stride-17 padded u64 length
#define XPHYS  (L + (L >> 4) + 2)          // padded x-pair length
#define EPS    1e-6f

typedef unsigned long long u64;

// compile-time window offset from (buf + 17*tid): logical pair 16*tid-15+k
#define OFS(k) ((k) + ((k) >> 4))
#define EPS2 0x358637BD358637BDULL         // (1e-6f,1e-6f)

// symmetric taps: tap j (0..30) lives in tapr[j<16 ? j : 30-j]
#define TAP(j) tapr[(j) < 16 ? (j) : (30 - (j))]

__device__ __forceinline__ u64 pk2(float lo, float hi) {
    u64 r;
    asm("mov.b64 %0, {%1, %2};" : "=l"(r) : "f"(lo), "f"(hi));
    return r;
}
__device__ __forceinline__ void upk2(u64 v, float &lo, float &hi) {
    asm("mov.b64 {%0, %1}, %2;" : "=f"(lo), "=f"(hi) : "l"(v));
}
// d = a*b + d on packed f32x2 (sm_100+; PTX-only)
__device__ __forceinline__ void fma2(u64 &d, u64 a, u64 b) {
    asm("fma.rn.f32x2 %0, %1, %2, %0;" : "+l"(d) : "l"(a), "l"(b));
}
// d = a*b + c (folds acc init into first contribution)
__device__ __forceinline__ void fma2a(u64 &d, u64 a, u64 b, u64 c) {
    asm("fma.rn.f32x2 %0, %1, %2, %3;" : "=l"(d) : "l"(a), "l"(b), "l"(c));
}
__device__ __forceinline__ u64 mul2(u64 a, u64 b) {
    u64 r;
    asm("mul.rn.f32x2 %0, %1, %2;" : "=l"(r) : "l"(a), "l"(b));
    return r;
}
__device__ __forceinline__ float frcp(float x) {
    float r;
    asm("rcp.approx.ftz.f32 %0, %1;" : "=f"(r) : "f"(x));
    return r;
}

__device__ __forceinline__ uint32_t s2u32(const void* p) {
    uint32_t a;
    asm("{ .reg .u64 t; cvta.to.shared.u64 t, %1; cvt.u32.u64 %0, t; }" : "=r"(a) : "l"(p));
    return a;
}
__device__ __forceinline__ void mbar_init(uint32_t addr, uint32_t cnt) {
    asm volatile("mbarrier.init.shared.b64 [%0], %1;" :: "r"(addr), "r"(cnt) : "memory");
}
__device__ __forceinline__ void mbar_arrive(uint32_t addr) {
    asm volatile("mbarrier.arrive.release.cta.shared::cta.b64 _, [%0];" :: "r"(addr) : "memory");
}
__device__ __forceinline__ void mbar_wait(uint32_t addr, uint32_t parity) {
    asm volatile(
        "{\n\t"
        ".reg .pred P;\n"
        "WL_%=:\n\t"
        "mbarrier.try_wait.parity.acquire.cta.shared::cta.b64 P, [%0], %1, 0x989680;\n\t"
        "@P bra WD_%=;\n\t"
        "bra WL_%=;\n"
        "WD_%=:\n\t"
        "}"
        :: "r"(addr), "r"(parity) : "memory");
}

// own-pair contribution from registers (pass 1): 256 FMA2s, EPS folded into init
__device__ __forceinline__ void conv_own_init(const u64 own[CP], const u64 tapr[16],
                                              u64 acc[CP], u64 eps2) {
    #pragma unroll
    for (int p = 0; p < CP; ++p)
        fma2a(acc[p], own[0], TAP(15 - p), eps2);
    #pragma unroll
    for (int pp = 1; pp < CP; ++pp) {
        const u64 v = own[pp];
        #pragma unroll
        for (int p = 0; p < CP; ++p)
            fma2(acc[p], v, TAP(15 + pp - p));        // j in [0,30] always
    }
}

// own-pair contribution streamed from SMEM (pass 2): 16 LDS.64 + 256 FMA2s,
// reads this thread's OWN slice (no barrier needed), ~2 live value regs
__device__ __forceinline__ void conv_own_stream(const u64* __restrict__ base,
                                                const u64 tapr[16],
                                                u64 acc[CP], u64 eps2) {
    {
        const u64 v = base[OFS(HALF + 0)];
        #pragma unroll
        for (int p = 0; p < CP; ++p)
            fma2a(acc[p], v, TAP(15 - p), eps2);
    }
    #pragma unroll
    for (int pp = 1; pp < CP; ++pp) {
        const u64 v = base[OFS(HALF + pp)];
        #pragma unroll
        for (int p = 0; p < CP; ++p)
            fma2(acc[p], v, TAP(15 + pp - p));
    }
}

// neighbor contributions: 30 LDS.64 + 240 FMA2s (triangular tap pattern)
__device__ __forceinline__ void conv_nbr(const u64* __restrict__ base,
                                         const u64 tapr[16], u64 acc[CP]) {
    #pragma unroll
    for (int k = 0; k < HALF; ++k) {             // left neighbor pairs, window pos 0..14
        const u64 v = base[OFS(k)];
        #pragma unroll
        for (int p = 0; p <= k; ++p)
            fma2(acc[p], v, TAP(k - p));
    }
    #pragma unroll
    for (int k = KK; k < KK + HALF; ++k) {       // right neighbor pairs, window pos 31..45
        const u64 v = base[OFS(k)];
        #pragma unroll
        for (int p = k - 30; p < CP; ++p)
            fma2(acc[p], v, TAP(k - p));
    }
}

__global__ void __launch_bounds__(NT, 1)
drl_kernel(const float* __restrict__ m,
           const float* __restrict__ psf,
           const float* __restrict__ alpha,
           float* __restrict__ out,
           int nlayers) {
    extern __shared__ u64 smbuf[];
    u64* S = smbuf;                 // estimate pairs (lo=row0, hi=row1), zero halos
    u64* T = smbuf + PHYS64;        // ratio pairs, zero halos
    u64* X = smbuf + 2 * PHYS64;    // pre-paired x, padded (no halo)
    __shared__ u64 mb[2 * NW];      // [w]=S barrier of warp w, [NW+w]=T barrier

    const int tid  = threadIdx.x;
    const int w    = tid >> 5;
    const int lane = tid & 31;
    const uint32_t mbase = s2u32(mb);
    const uint32_t sOwn = mbase + 8u * w;
    const uint32_t tOwn = mbase + 8u * (NW + w);

    if (tid < 2 * NW) {
        int ww = tid & (NW - 1);
        uint32_t cnt = 1u + (ww > 0) + (ww < NW - 1);   // self + existing neighbors
        mbar_init(mbase + 8u * tid, cnt);
    }

    // taps into 16 registers; PSF symmetric (bit-exact), so flip == forward
    u64 tapr[16];
    #pragma unroll
    for (int t = 0; t < 16; ++t) {
        float wv = psf[t];
        tapr[t] = pk2(wv, wv);
    }
    const u64 eps2 = EPS2;

    // init SMEM: S = 0.5 inside / 0 halos; T = 0 (halos stay 0 forever)
    for (int u = tid; u < ULEN; u += NT) {
        int i = u - HALF;
        float v = (i >= 0 && i < L) ? 0.5f : 0.0f;
        S[u + (u >> 4)] = pk2(v, v);
        T[u + (u >> 4)] = 0ull;
    }

    const int b = tid * CP;
    u64* const Sb = S + 17 * tid;        // base at logical pair b-15
    u64* const Tb = T + 17 * tid;
    u64* const Xb = X + 17 * tid;        // Xb[OFS(p)] = x pair b+p

    // x: two rows per CTA, one coalesced HBM read, pre-paired into SMEM
    {
        const float* m0 = m + (size_t)(2 * blockIdx.x) * L + b;
        const float* m1 = m0 + L;
        #pragma unroll
        for (int q = 0; q < 4; ++q) {
            float4 a0 = ((const float4*)m0)[q];
            float4 a1 = ((const float4*)m1)[q];
            Xb[OFS(q * 4 + 0)] = pk2(a0.x, a1.x);
            Xb[OFS(q * 4 + 1)] = pk2(a0.y, a1.y);
            Xb[OFS(q * 4 + 2)] = pk2(a0.z, a1.z);
            Xb[OFS(q * 4 + 3)] = pk2(a0.w, a1.w);
        }
    }

    // own S pairs live in registers across layers
    u64 sreg[CP];
    #pragma unroll
    for (int p = 0; p < CP; ++p) sreg[p] = pk2(0.5f, 0.5f);

    __syncthreads();                 // mbarrier init + S/T/X init visible CTA-wide

    // initial "S ready": each warp signals the barriers of its consumers (w-1, w, w+1)
    if (lane == 0) {
        if (w > 0)      mbar_arrive(mbase + 8u * (w - 1));
        mbar_arrive(sOwn);
        if (w < NW - 1) mbar_arrive(mbase + 8u * (w + 1));
    }

    uint32_t parS = 0, parT = 0;

    for (int layer = 0; layer < nlayers; ++layer) {
        const float a = alpha[layer];
        u64 acc[CP];

        // ---- pass 1: s_conv = conv(S)+EPS; ratio = x / s_conv -> T(SMEM) ----
        if (layer == 0 && w >= 1 && w <= NW - 2) {
            // S==0.5 and taps sum to 1: interior warps skip the conv entirely
            #pragma unroll
            for (int p = 0; p < CP; ++p) acc[p] = pk2(0.5f + EPS, 0.5f + EPS);
        } else {
            conv_own_init(sreg, tapr, acc, eps2);  // overlaps neighbors' S stores
            mbar_wait(sOwn, parS);                 // only my 3-warp neighborhood
            conv_nbr(Sb, tapr, acc);
        }
        parS ^= 1;

        #pragma unroll
        for (int p = 0; p < CP; ++p) {
            // paired reciprocal: (xa/sa, xb/sb) = (xa*sb, xb*sa) * rcp(sa*sb)
            float sa, sb;
            upk2(acc[p], sa, sb);
            float r = frcp(sa * sb);
            u64 num = mul2(Xb[OFS(p)], pk2(sb, sa));
            Tb[OFS(p + HALF)] = mul2(num, pk2(r, r));
        }
        __syncwarp();
        if (lane == 0) {                           // T ready for my consumers
            if (w > 0)      mbar_arrive(mbase + 8u * (NW + w - 1));
            mbar_arrive(tOwn);
            if (w < NW - 1) mbar_arrive(mbase + 8u * (NW + w + 1));
        }

        // ---- pass 2: corr = max(conv(T)+EPS, EPS); S = max(S*corr^a, EPS) ----
        conv_own_stream(Tb, tapr, acc, eps2);      // own T from SMEM; overlaps nbr stores
        mbar_wait(tOwn, parT); parT ^= 1;
        conv_nbr(Tb, tapr, acc);

        #pragma unroll
        for (int p = 0; p < CP; ++p) {
            float ca, cb;
            upk2(acc[p], ca, cb);
            ca = fmaxf(ca, EPS);
            cb = fmaxf(cb, EPS);
            if (a != 1.0f) {                       // warp-uniform; skipped for alpha==1
                ca = __powf(ca, a);
                cb = __powf(cb, a);
            }
            u64 sc = mul2(sreg[p], pk2(ca, cb));
            float so, sh;
            upk2(sc, so, sh);
            so = fmaxf(so, EPS);
            sh = fmaxf(sh, EPS);
            sreg[p] = pk2(so, sh);
        }
        if (layer + 1 < nlayers) {                 // publish S for next layer
            #pragma unroll
            for (int p = 0; p < CP; ++p)
                Sb[OFS(p + HALF)] = sreg[p];
            __syncwarp();
            if (lane == 0) {
                if (w > 0)      mbar_arrive(mbase + 8u * (w - 1));
                mbar_arrive(sOwn);
                if (w < NW - 1) mbar_arrive(mbase + 8u * (w + 1));
            }
        }
    }

    // coalesced output: unpack register pairs into the two rows
    {
        float* o0 = out + (size_t)(2 * blockIdx.x) * L + b;
        float* o1 = o0 + L;
        #pragma unroll
        for (int q = 0; q < 4; ++q) {
            float4 v0, v1;
            float lo, hi;
            upk2(sreg[q * 4 + 0], lo, hi); v0.x = lo; v1.x = hi;
            upk2(sreg[q * 4 + 1], lo, hi); v0.y = lo; v1.y = hi;
            upk2(sreg[q * 4 + 2], lo, hi); v0.z = lo; v1.z = hi;
            upk2(sreg[q * 4 + 3], lo, hi); v0.w = lo; v1.w = hi;
            ((float4*)o0)[q] = v0;
            ((float4*)o1)[q] = v1;
        }
    }
}

extern "C" void kernel_launch(void* const* d_in, const int* in_sizes, int n_in,
                              void* d_out, int out_size) {
    const float* m     = (const float*)d_in[0];
    const float* psf   = (const float*)d_in[1];
    const float* alpha = (const float*)d_in[2];
    float* out = (float*)d_out;

    const int nlayers = in_sizes[2];
    const int B = in_sizes[0] / L;
    const int grid = B / 2;                        // two rows per CTA
    const int smem_bytes = (2 * PHYS64 + XPHYS) * (int)sizeof(u64);

    cudaFuncSetAttribute(drl_kernel, cudaFuncAttributeMaxDynamicSharedMemorySize, smem_bytes);
    drl_kernel<<<grid, NT, smem_bytes>>>(m, psf, alpha, out, nlayers);
}

// round 17
// speedup vs baseline: 1.1037x; 1.1037x over previous
#include <cuda_runtime.h>
#include <cstdint>

#define L      8192
#define KK     31
#define HALF   15
#define NT     512
#define NW     16                          // warps per CTA
#define CP     16                          // output pairs per thread
#define ULEN   (L + 2*HALF)                // 8222 pairs incl zero halos
#define PHYS64 (ULEN + (ULEN >> 4) + 2)    // stride-17 padded u64 length
#define EPS    1e-6f

typedef unsigned long long u64;

// compile-time window offset from (buf + 17*tid): logical pair 16*tid-15+k
#define OFS(k) ((k) + ((k) >> 4))
#define EPS2 0x358637BD358637BDULL         // (1e-6f,1e-6f)

// symmetric taps: tap j (0..30) lives in tapr[j<16 ? j : 30-j]
#define TAP(j) tapr[(j) < 16 ? (j) : (30 - (j))]

__device__ __forceinline__ u64 pk2(float lo, float hi) {
    u64 r;
    asm("mov.b64 %0, {%1, %2};" : "=l"(r) : "f"(lo), "f"(hi));
    return r;
}
__device__ __forceinline__ void upk2(u64 v, float &lo, float &hi) {
    asm("mov.b64 {%0, %1}, %2;" : "=f"(lo), "=f"(hi) : "l"(v));
}
// d = a*b + d on packed f32x2 (sm_100+; PTX-only)
__device__ __forceinline__ void fma2(u64 &d, u64 a, u64 b) {
    asm("fma.rn.f32x2 %0, %1, %2, %0;" : "+l"(d) : "l"(a), "l"(b));
}
// d = a*b + c (folds acc init into first contribution)
__device__ __forceinline__ void fma2a(u64 &d, u64 a, u64 b, u64 c) {
    asm("fma.rn.f32x2 %0, %1, %2, %3;" : "=l"(d) : "l"(a), "l"(b), "l"(c));
}
__device__ __forceinline__ u64 mul2(u64 a, u64 b) {
    u64 r;
    asm("mul.rn.f32x2 %0, %1, %2;" : "=l"(r) : "l"(a), "l"(b));
    return r;
}
__device__ __forceinline__ float frcp(float x) {
    float r;
    asm("rcp.approx.ftz.f32 %0, %1;" : "=f"(r) : "f"(x));
    return r;
}

__device__ __forceinline__ uint32_t s2u32(const void* p) {
    uint32_t a;
    asm("{ .reg .u64 t; cvta.to.shared.u64 t, %1; cvt.u32.u64 %0, t; }" : "=r"(a) : "l"(p));
    return a;
}
__device__ __forceinline__ void mbar_init(uint32_t addr, uint32_t cnt) {
    asm volatile("mbarrier.init.shared.b64 [%0], %1;" :: "r"(addr), "r"(cnt) : "memory");
}
__device__ __forceinline__ void mbar_arrive(uint32_t addr) {
    asm volatile("mbarrier.arrive.release.cta.shared::cta.b64 _, [%0];" :: "r"(addr) : "memory");
}
__device__ __forceinline__ void mbar_wait(uint32_t addr, uint32_t parity) {
    asm volatile(
        "{\n\t"
        ".reg .pred P;\n"
        "WL_%=:\n\t"
        "mbarrier.try_wait.parity.acquire.cta.shared::cta.b64 P, [%0], %1, 0x989680;\n\t"
        "@P bra WD_%=;\n\t"
        "bra WL_%=;\n"
        "WD_%=:\n\t"
        "}"
        :: "r"(addr), "r"(parity) : "memory");
}

// own-pair contribution with folded EPS init: 256 FMA2s, no SMEM, no init MOVs
__device__ __forceinline__ void conv_own_init(const u64 own[CP], const u64 tapr[16],
                                              u64 acc[CP], u64 eps2) {
    #pragma unroll
    for (int p = 0; p < CP; ++p)
        fma2a(acc[p], own[0], TAP(15 - p), eps2);     // pp=0 seeds acc with EPS
    #pragma unroll
    for (int pp = 1; pp < CP; ++pp) {
        const u64 v = own[pp];
        #pragma unroll
        for (int p = 0; p < CP; ++p)
            fma2(acc[p], v, TAP(15 + pp - p));        // j in [0,30] always
    }
}

// neighbor contributions: 30 LDS.64 + 240 FMA2s (triangular tap pattern)
__device__ __forceinline__ void conv_nbr(const u64* __restrict__ base,
                                         const u64 tapr[16], u64 acc[CP]) {
    #pragma unroll
    for (int k = 0; k < HALF; ++k) {             // left neighbor pairs, window pos 0..14
        const u64 v = base[OFS(k)];
        #pragma unroll
        for (int p = 0; p <= k; ++p)
            fma2(acc[p], v, TAP(k - p));
    }
    #pragma unroll
    for (int k = KK; k < KK + HALF; ++k) {       // right neighbor pairs, window pos 31..45
        const u64 v = base[OFS(k)];
        #pragma unroll
        for (int p = k - 30; p < CP; ++p)
            fma2(acc[p], v, TAP(k - p));
    }
}

__global__ void __launch_bounds__(NT, 1)
drl_kernel(const float* __restrict__ m,
           const float* __restrict__ psf,
           const float* __restrict__ alpha,
           float* __restrict__ out,
           int nlayers) {
    extern __shared__ u64 smbuf[];
    u64* S = smbuf;                 // estimate pairs (lo=row0, hi=row1), zero halos
    u64* T = smbuf + PHYS64;        // ratio pairs, zero halos
    __shared__ u64 mb[2 * NW];      // [w]=S barrier of warp w, [NW+w]=T barrier

    const int tid  = threadIdx.x;
    const int w    = tid >> 5;
    const int lane = tid & 31;
    const uint32_t mbase = s2u32(mb);
    const uint32_t sOwn = mbase + 8u * w;
    const uint32_t tOwn = mbase + 8u * (NW + w);

    if (tid < 2 * NW) {
        int ww = tid & (NW - 1);
        uint32_t cnt = 1u + (ww > 0) + (ww < NW - 1);   // arrivals: self + existing neighbors
        mbar_init(mbase + 8u * tid, cnt);
    }

    // taps into 16 registers; PSF symmetric (bit-exact), so flip == forward
    u64 tapr[16];
    #pragma unroll
    for (int t = 0; t < 16; ++t) {
        float wv = psf[t];
        tapr[t] = pk2(wv, wv);
    }
    const u64 eps2 = EPS2;

    // init SMEM: S = 0.5 inside / 0 halos; T = 0 (halos stay 0 forever)
    for (int u = tid; u < ULEN; u += NT) {
        int i = u - HALF;
        float v = (i >= 0 && i < L) ? 0.5f : 0.0f;
        S[u + (u >> 4)] = pk2(v, v);
        T[u + (u >> 4)] = 0ull;
    }

    const int b = tid * CP;
    u64* const Sb = S + 17 * tid;        // base at logical pair b-15
    u64* const Tb = T + 17 * tid;

    // x: two rows per CTA, one coalesced HBM read into 16 registers
    u64 xr[CP];
    {
        const float* m0 = m + (size_t)(2 * blockIdx.x) * L + b;
        const float* m1 = m0 + L;
        #pragma unroll
        for (int q = 0; q < 4; ++q) {
            float4 a0 = ((const float4*)m0)[q];
            float4 a1 = ((const float4*)m1)[q];
            xr[q * 4 + 0] = pk2(a0.x, a1.x);
            xr[q * 4 + 1] = pk2(a0.y, a1.y);
            xr[q * 4 + 2] = pk2(a0.z, a1.z);
            xr[q * 4 + 3] = pk2(a0.w, a1.w);
        }
    }

    // own S pairs live in registers for the whole kernel
    u64 sreg[CP];
    #pragma unroll
    for (int p = 0; p < CP; ++p) sreg[p] = pk2(0.5f, 0.5f);

    __syncthreads();                 // mbarrier init + S/T init visible CTA-wide

    // initial "S ready": each warp signals the barriers of its consumers (w-1, w, w+1)
    if (lane == 0) {
        if (w > 0)      mbar_arrive(mbase + 8u * (w - 1));
        mbar_arrive(sOwn);
        if (w < NW - 1) mbar_arrive(mbase + 8u * (w + 1));
    }

    uint32_t parS = 0, parT = 0;

    for (int layer = 0; layer < nlayers; ++layer) {
        const float a = alpha[layer];
        u64 acc[CP];

        // ---- pass 1: s_conv = conv(S)+EPS; ratio = x / s_conv ----
        if (layer == 0 && w >= 1 && w <= NW - 2) {
            // S==0.5 and taps sum to 1: interior warps skip the conv entirely
            #pragma unroll
            for (int p = 0; p < CP; ++p) acc[p] = pk2(0.5f + EPS, 0.5f + EPS);
        } else {
            conv_own_init(sreg, tapr, acc, eps2);  // overlaps neighbors' S stores
            mbar_wait(sOwn, parS);                 // only my 3-warp neighborhood
            conv_nbr(Sb, tapr, acc);
        }
        parS ^= 1;

        u64 treg[CP];
        #pragma unroll
        for (int p = 0; p < CP; ++p) {
            // paired reciprocal: (xa/sa, xb/sb) = (xa*sb, xb*sa) * rcp(sa*sb)
            float sa, sb;
            upk2(acc[p], sa, sb);
            float r = frcp(sa * sb);
            u64 num = mul2(xr[p], pk2(sb, sa));
            treg[p] = mul2(num, pk2(r, r));
            Tb[OFS(p + HALF)] = treg[p];
        }
        __syncwarp();
        if (lane == 0) {                           // T ready for my consumers
            if (w > 0)      mbar_arrive(mbase + 8u * (NW + w - 1));
            mbar_arrive(tOwn);
            if (w < NW - 1) mbar_arrive(mbase + 8u * (NW + w + 1));
        }

        // ---- pass 2: corr = conv(T)+EPS (>= EPS by construction, clamp is a no-op);
        //              S = max(S * corr^a, EPS) ----
        conv_own_init(treg, tapr, acc, eps2);      // overlaps neighbors' T stores
        mbar_wait(tOwn, parT); parT ^= 1;
        conv_nbr(Tb, tapr, acc);

        #pragma unroll
        for (int p = 0; p < CP; ++p) {
            u64 corr = acc[p];                     // conv(T)+EPS >= EPS always
            if (a != 1.0f) {                       // warp-uniform; skipped for alpha==1
                float ca, cb;
                upk2(corr, ca, cb);
                corr = pk2(__powf(ca, a), __powf(cb, a));
            }
            u64 sc = mul2(sreg[p], corr);
            float so, sh;
            upk2(sc, so, sh);
            so = fmaxf(so, EPS);                   // this clamp CAN bind (x < 1e-6)
            sh = fmaxf(sh, EPS);
            sreg[p] = pk2(so, sh);
        }
        if (layer + 1 < nlayers) {                 // publish S for next layer
            #pragma unroll
            for (int p = 0; p < CP; ++p)
                Sb[OFS(p + HALF)] = sreg[p];
            __syncwarp();
            if (lane == 0) {
                if (w > 0)      mbar_arrive(mbase + 8u * (w - 1));
                mbar_arrive(sOwn);
                if (w < NW - 1) mbar_arrive(mbase + 8u * (w + 1));
            }
        }
    }

    // coalesced output: unpack register pairs into the two rows
    {
        float* o0 = out + (size_t)(2 * blockIdx.x) * L + b;
        float* o1 = o0 + L;
        #pragma unroll
        for (int q = 0; q < 4; ++q) {
            float4 v0, v1;
            float lo, hi;
            upk2(sreg[q * 4 + 0], lo, hi); v0.x = lo; v1.x = hi;
            upk2(sreg[q * 4 + 1], lo, hi); v0.y = lo; v1.y = hi;
            upk2(sreg[q * 4 + 2], lo, hi); v0.z = lo; v1.z = hi;
            upk2(sreg[q * 4 + 3], lo, hi); v0.w = lo; v1.w = hi;
            ((float4*)o0)[q] = v0;
            ((float4*)o1)[q] = v1;
        }
    }
}

extern "C" void kernel_launch(void* const* d_in, const int* in_sizes, int n_in,
                              void* d_out, int out_size) {
    const float* m     = (const float*)d_in[0];
    const float* psf   = (const float*)d_in[1];
    const float* alpha = (const float*)d_in[2];
    float* out = (float*)d_out;

    const int nlayers = in_sizes[2];
    const int B = in_sizes[0] / L;
    const int grid = B / 2;                        // two rows per CTA
    const int smem_bytes = 2 * PHYS64 * (int)sizeof(u64);

    cudaFuncSetAttribute(drl_kernel, cudaFuncAttributeMaxDynamicSharedMemorySize, smem_bytes);
    drl_kernel<<<grid, NT, smem_bytes>>>(m, psf, alpha, out, nlayers);
}